// round 8
// baseline (speedup 1.0000x reference)
#include <cuda_runtime.h>
#include <math.h>
#include <stdint.h>

// Problem constants
#define BB 8
#define TT 256
#define DD 256      // q_size / feature dim
#define HH 128
#define WW 128
#define CS 512      // c_size
#define MM (BB*TT)  // 2048 rows
#define RR 9
#define CC 9
#define KK 81       // R*C
#define ROWS 129    // H+1
#define COLS 129    // W+1
#define QTOT (8LL*256LL*16384LL)   // total floats in q

// Scratch (device globals; no allocation allowed)
__device__ float g_h[MM * 256];   // pre-tanh hidden (W_p path)
__device__ float g_u[MM * 256];   // u = c_t @ W_a
__device__ float g_p[MM * 2];     // p_t

// ---------------------------------------------------------------------------
// Kernel 1: fused GEMM using packed fma.rn.f32x2 (FFMA2).
//   n <  256 : g_h[m][n]      = sum_c c_t[m,c] * W_p[n,c]
//   n >= 256 : g_u[m][n-256]  = sum_c c_t[m,c] * W_a[c,n-256]
// BM=128, BN=64, BK=16, 128 threads, 8x8 micro-tile as 4 m-pairs x 8 n.
// A staged transposed As[k][m] -> ulonglong2 loads give (m,m+1) packed pairs.
// B staged duplicated (b,b) in chunks of 4 n (8 floats) at stride 20 floats
// (bank-spread, <=2-way) -> ulonglong2 loads give dup-pair operands directly.
// Dynamic smem: As 2*16*132 floats, then Bs 2*16*320 floats (57,856 B total).
// ---------------------------------------------------------------------------
#define AS_STRIDE 132
#define BS_STRIDE 320
#define AS_BUF (16 * AS_STRIDE)          // 2112 floats per buffer
#define BS_BUF (16 * BS_STRIDE)          // 5120 floats per buffer
#define BS_BASE (2 * AS_BUF)             // Bs starts after As
#define GEMM_SMEM ((2 * AS_BUF + 2 * BS_BUF) * 4)   // 57856 bytes

__global__ __launch_bounds__(128)
void gemm_kernel(const float* __restrict__ A,   // c_t (2048,512)
                 const float* __restrict__ Wp,  // (256,512)
                 const float* __restrict__ Wa)  // (512,256)
{
    extern __shared__ float sm[];
    float* Asm = sm;                 // [buf][k][m]  k*132 + m
    float* Bsm = sm + BS_BASE;       // [buf][k][x]  k*320 + chunk*20 (+ dup pairs)

    const int m0 = blockIdx.x * 128;
    const int n0 = blockIdx.y * 64;
    const bool is_u = (n0 >= 256);
    const int tid = threadIdx.x;
    const int tx = tid & 7;         // n group: n = tx*8 + j
    const int ty = tid >> 3;        // m group: m = ty*8 + ...

    float4 ra[4], rb[2];

    auto ldg_tile = [&](int k0) {
#pragma unroll
        for (int s = 0; s < 4; s++) {
            int f = tid + s * 128;
            ra[s] = *(const float4*)(A + (size_t)(m0 + (f >> 2)) * CS + k0 + ((f & 3) << 2));
        }
        if (!is_u) {
#pragma unroll
            for (int s = 0; s < 2; s++) {
                int f = tid + s * 128;
                rb[s] = *(const float4*)(Wp + (size_t)(n0 + (f >> 2)) * CS + k0 + ((f & 3) << 2));
            }
        } else {
#pragma unroll
            for (int s = 0; s < 2; s++) {
                int f = tid + s * 128;
                rb[s] = *(const float4*)(Wa + (size_t)(k0 + (f >> 4)) * 256 + (n0 - 256) + ((f & 15) << 2));
            }
        }
    };

    auto sts_tile = [&](int bf) {
        float* Ab = Asm + bf * AS_BUF;
        float* Bb = Bsm + bf * BS_BUF;
#pragma unroll
        for (int s = 0; s < 4; s++) {
            int f = tid + s * 128;
            int row = f >> 2, kk = (f & 3) << 2;
            Ab[(kk + 0) * AS_STRIDE + row] = ra[s].x;
            Ab[(kk + 1) * AS_STRIDE + row] = ra[s].y;
            Ab[(kk + 2) * AS_STRIDE + row] = ra[s].z;
            Ab[(kk + 3) * AS_STRIDE + row] = ra[s].w;
        }
        if (!is_u) {
#pragma unroll
            for (int s = 0; s < 2; s++) {
                int f = tid + s * 128;
                int n = f >> 2, kk = (f & 3) << 2;
                int coff = (n >> 2) * 20 + (n & 3) * 2;   // max 306 (+2) < 320
                float vv[4] = {rb[s].x, rb[s].y, rb[s].z, rb[s].w};
#pragma unroll
                for (int i = 0; i < 4; i++)
                    *(float2*)&Bb[(kk + i) * BS_STRIDE + coff] = make_float2(vv[i], vv[i]);
            }
        } else {
#pragma unroll
            for (int s = 0; s < 2; s++) {
                int f = tid + s * 128;
                int k = f >> 4, nn = (f & 15) << 2;
                int c = nn >> 2;                          // max offset 300+8 = 308 < 320
                *(float4*)&Bb[k * BS_STRIDE + c * 20]     = make_float4(rb[s].x, rb[s].x, rb[s].y, rb[s].y);
                *(float4*)&Bb[k * BS_STRIDE + c * 20 + 4] = make_float4(rb[s].z, rb[s].z, rb[s].w, rb[s].w);
            }
        }
    };

    unsigned long long acc[4][8];
#pragma unroll
    for (int mp = 0; mp < 4; mp++)
#pragma unroll
        for (int j = 0; j < 8; j++) acc[mp][j] = 0ull;

    ldg_tile(0);
    sts_tile(0);
    __syncthreads();

    int buf = 0;
    for (int t = 0; t < 32; t++) {
        if (t < 31) ldg_tile((t + 1) * 16);
        {
            const float* Ab = Asm + buf * AS_BUF;
            const float* Bb = Bsm + buf * BS_BUF;
#pragma unroll
            for (int k = 0; k < 16; k++) {
                ulonglong2 a01 = *(const ulonglong2*)&Ab[k * AS_STRIDE + ty * 8];
                ulonglong2 a23 = *(const ulonglong2*)&Ab[k * AS_STRIDE + ty * 8 + 4];
                ulonglong2 b01 = *(const ulonglong2*)&Bb[k * BS_STRIDE + (2 * tx) * 20];
                ulonglong2 b23 = *(const ulonglong2*)&Bb[k * BS_STRIDE + (2 * tx) * 20 + 4];
                ulonglong2 b45 = *(const ulonglong2*)&Bb[k * BS_STRIDE + (2 * tx + 1) * 20];
                ulonglong2 b67 = *(const ulonglong2*)&Bb[k * BS_STRIDE + (2 * tx + 1) * 20 + 4];
                unsigned long long av[4] = {a01.x, a01.y, a23.x, a23.y};
                unsigned long long bv[8] = {b01.x, b01.y, b23.x, b23.y,
                                            b45.x, b45.y, b67.x, b67.y};
#pragma unroll
                for (int mp = 0; mp < 4; mp++)
#pragma unroll
                    for (int j = 0; j < 8; j++)
                        asm("fma.rn.f32x2 %0, %1, %2, %0;"
                            : "+l"(acc[mp][j]) : "l"(av[mp]), "l"(bv[j]));
            }
        }
        if (t < 31) { sts_tile(buf ^ 1); __syncthreads(); }
        buf ^= 1;
    }

    // Epilogue: acc[mp][j] holds rows (ty*8+2mp, +1) packed; cols n0 + tx*8 + j
    float* dst = is_u ? g_u : g_h;
    const size_t noff = (size_t)(is_u ? (n0 - 256) : n0) + tx * 8;
#pragma unroll
    for (int mp = 0; mp < 4; mp++) {
        float lo[8], hi[8];
#pragma unroll
        for (int j = 0; j < 8; j++) {
            float2 v = *(float2*)&acc[mp][j];
            lo[j] = v.x; hi[j] = v.y;
        }
        int mr0 = m0 + ty * 8 + mp * 2;
        float* d0 = dst + (size_t)mr0 * 256 + noff;
        float* d1 = dst + (size_t)(mr0 + 1) * 256 + noff;
        *(float4*)(d0)     = make_float4(lo[0], lo[1], lo[2], lo[3]);
        *(float4*)(d0 + 4) = make_float4(lo[4], lo[5], lo[6], lo[7]);
        *(float4*)(d1)     = make_float4(hi[0], hi[1], hi[2], hi[3]);
        *(float4*)(d1 + 4) = make_float4(hi[4], hi[5], hi[6], hi[7]);
    }
}

// ---------------------------------------------------------------------------
// Kernel 2: p_t = 128 * sigmoid( tanh(h) @ V_p^T ).  One warp per row,
// 8 rows per 256-thread block.
// ---------------------------------------------------------------------------
__global__ __launch_bounds__(256)
void p_kernel(const float* __restrict__ Vp)  // (2,256)
{
    const int m = blockIdx.x * 8 + (threadIdx.x >> 5);
    const int lane = threadIdx.x & 31;
    float s0 = 0.f, s1 = 0.f;
#pragma unroll
    for (int n = lane; n < 256; n += 32) {
        float hv = tanhf(g_h[(size_t)m * 256 + n]);
        s0 = fmaf(hv, Vp[n], s0);
        s1 = fmaf(hv, Vp[256 + n], s1);
    }
#pragma unroll
    for (int off = 16; off > 0; off >>= 1) {
        s0 += __shfl_xor_sync(0xffffffffu, s0, off);
        s1 += __shfl_xor_sync(0xffffffffu, s1, off);
    }
    if (lane == 0) {
        g_p[m * 2 + 0] = 128.f / (1.f + expf(-s0));
        g_p[m * 2 + 1] = 128.f / (1.f + expf(-s1));
    }
}

// ---------------------------------------------------------------------------
// Vectorized gather: each thread owns feature d = tid and loads its 9 window
// rows as 3 aligned float4s covering cols a0..a0+11; the 9 needed values sit
// at uniform offset OFF = (cb-4)&3. Invalid slots (clipped/wrapped -> NaN in
// reference) get softmax weight 0, so any finite value is acceptable there.
// ---------------------------------------------------------------------------
template<int OFF>
__device__ __forceinline__ void gather_rows(const float* __restrict__ q,
                                            long long gbase,   // b*4194304 + d*16384 + a0
                                            const int* __restrict__ sri,
                                            float* __restrict__ srow)  // &s[d*81]
{
#pragma unroll 3
    for (int i = 0; i < 9; i++) {
        int rv = sri[i];
        float f[12];
        if (rv > 0) {
            long long g = gbase + (long long)(rv - 1) * 128;
            if (g >= 0 && g + 12 <= QTOT) {
                float4 v0 = __ldg((const float4*)(q + g));
                float4 v1 = __ldg((const float4*)(q + g + 4));
                float4 v2 = __ldg((const float4*)(q + g + 8));
                f[0] = v0.x; f[1] = v0.y; f[2]  = v0.z; f[3]  = v0.w;
                f[4] = v1.x; f[5] = v1.y; f[6]  = v1.z; f[7]  = v1.w;
                f[8] = v2.x; f[9] = v2.y; f[10] = v2.z; f[11] = v2.w;
            } else {
                // Rare buffer-edge fallback
#pragma unroll
                for (int x = 0; x < 12; x++) {
                    long long gg = g + x;
                    f[x] = (gg >= 0 && gg < QTOT) ? __ldg(q + gg) : 0.f;
                }
            }
        } else {
#pragma unroll
            for (int x = 0; x < 12; x++) f[x] = 0.f;
        }
#pragma unroll
        for (int j = 0; j < 9; j++) srow[i * 9 + j] = f[OFF + j];
    }
}

// ---------------------------------------------------------------------------
// Kernel 3: main local attention. One CTA per (b,t). 256 threads.
// ---------------------------------------------------------------------------
__global__ __launch_bounds__(256)
void attn_kernel(const float* __restrict__ q, float* __restrict__ out)
{
    extern __shared__ float s[];           // [256][81] window, layout d*81+k
    __shared__ float su[256];
    __shared__ float spart[3 * KK];
    __shared__ float sa[KK];
    __shared__ float sw[KK];
    __shared__ float sred[2];
    __shared__ int   sri[RR], sci[CC];
    __shared__ float srex[RR], scex[CC];
    __shared__ int   scb;                  // rint(p1)

    const int t = blockIdx.x;
    const int b = blockIdx.y;
    const int m = b * TT + t;
    const int tid = threadIdx.x;

    // u vector
    su[tid] = g_u[(size_t)m * 256 + tid];
    const float p0 = g_p[m * 2 + 0];
    const float p1 = g_p[m * 2 + 1];

    // indices + gaussian terms
    if (tid < RR) {
        int cr = (int)rintf(p0);
        int v = cr + tid - 3;                  // round(p0) + off + 1, off = tid-4
        v = min(max(v, 0), ROWS);
        if (v == ROWS) v = 0;
        sri[tid] = v;
        float rr = (float)max(v - 1, 0);
        float d = (rr - p0) * 0.25f;
        srex[tid] = -2.f * d * d;
    } else if (tid < RR + CC) {
        int i = tid - RR;
        int cc = (int)rintf(p1);
        if (i == 0) scb = cc;
        int v = cc + i - 3;
        v = min(max(v, 0), COLS);
        if (v == COLS) v = 0;
        sci[i] = v;
        float ccf = (float)max(v - 1, 0);
        float d = (ccf - p1) * 0.25f;
        scex[i] = -2.f * d * d;
    }
    __syncthreads();

    // Gather window into smem: s[d*81 + k], k = i*9 + j, d = tid
    {
        const int cb = scb;
        const int a0 = (cb - 4) & ~3;          // aligned col start (may be -4)
        const int off = (cb - 4) & 3;          // uniform 0..3
        const long long gbase = (long long)b * 4194304LL
                              + (long long)tid * 16384LL + a0;
        float* srow = &s[tid * KK];
        switch (off) {
            case 0: gather_rows<0>(q, gbase, sri, srow); break;
            case 1: gather_rows<1>(q, gbase, sri, srow); break;
            case 2: gather_rows<2>(q, gbase, sri, srow); break;
            default: gather_rows<3>(q, gbase, sri, srow); break;
        }
    }
    __syncthreads();

    // Scores: a[k] = sum_d u[d] * s[d][k], split over 3 d-partitions
    if (tid < 3 * KK) {
        int k = tid % KK;
        int part = tid / KK;
        float acc0 = 0.f, acc1 = 0.f;
        int d = part;
        for (; d + 3 < 256; d += 6) {
            acc0 = fmaf(su[d],     s[d * KK + k],       acc0);
            acc1 = fmaf(su[d + 3], s[(d + 3) * KK + k], acc1);
        }
        for (; d < 256; d += 3)
            acc0 = fmaf(su[d], s[d * KK + k], acc0);
        spart[part * KK + k] = acc0 + acc1;
    }
    __syncthreads();

    if (tid < KK) {
        float a = spart[tid] + spart[KK + tid] + spart[2 * KK + tid];
        int i = tid / CC, j = tid - i * CC;
        bool valid = (sri[i] > 0) && (sci[j] > 0);
        sa[tid] = valid ? a : -INFINITY;
    }
    __syncthreads();

    // max
    if (tid < 32) {
        float mx = -INFINITY;
        for (int k = tid; k < KK; k += 32) mx = fmaxf(mx, sa[k]);
#pragma unroll
        for (int off = 16; off > 0; off >>= 1)
            mx = fmaxf(mx, __shfl_xor_sync(0xffffffffu, mx, off));
        if (tid == 0) sred[0] = mx;
    }
    __syncthreads();
    const float mx = sred[0];
    if (tid < KK) sa[tid] = expf(sa[tid] - mx);
    __syncthreads();
    if (tid < 32) {
        float sm = 0.f;
        for (int k = tid; k < KK; k += 32) sm += sa[k];
#pragma unroll
        for (int off = 16; off > 0; off >>= 1)
            sm += __shfl_xor_sync(0xffffffffu, sm, off);
        if (tid == 0) sred[1] = sm;
    }
    __syncthreads();
    const float inv = 1.f / sred[1];
    if (tid < KK) {
        int i = tid / CC, j = tid - i * CC;
        float g = expf(srex[i] + scex[j]);
        sw[tid] = sa[tid] * inv * g;
    }
    __syncthreads();

    // Output: out[m][d] = sum_k w[k] * s[d][k]
    float o0 = 0.f, o1 = 0.f, o2 = 0.f, o3 = 0.f;
    const float* sd = &s[tid * KK];
#pragma unroll
    for (int k = 0; k < 80; k += 4) {
        o0 = fmaf(sw[k + 0], sd[k + 0], o0);
        o1 = fmaf(sw[k + 1], sd[k + 1], o1);
        o2 = fmaf(sw[k + 2], sd[k + 2], o2);
        o3 = fmaf(sw[k + 3], sd[k + 3], o3);
    }
    o0 = fmaf(sw[80], sd[80], o0);
    out[(size_t)m * DD + tid] = (o0 + o1) + (o2 + o3);
}

// ---------------------------------------------------------------------------
extern "C" void kernel_launch(void* const* d_in, const int* in_sizes, int n_in,
                              void* d_out, int out_size)
{
    const float* q   = (const float*)d_in[0];   // (8,256,128,128)
    const float* c_t = (const float*)d_in[1];   // (8,256,512)
    const float* W_a = (const float*)d_in[2];   // (512,256)
    const float* W_p = (const float*)d_in[3];   // (256,512)
    const float* V_p = (const float*)d_in[4];   // (2,256)
    float* out = (float*)d_out;                 // (8,256,256)

    // Phase 1: projections (FFMA2 GEMM, dynamic smem)
    cudaFuncSetAttribute(gemm_kernel, cudaFuncAttributeMaxDynamicSharedMemorySize, GEMM_SMEM);
    gemm_kernel<<<dim3(MM / 128, 512 / 64), 128, GEMM_SMEM>>>(c_t, W_p, W_a);
    // Phase 2: p_t
    p_kernel<<<MM / 8, 256>>>(V_p);
    // Phase 3: attention
    const int smem = KK * DD * (int)sizeof(float);  // 82944 bytes
    cudaFuncSetAttribute(attn_kernel, cudaFuncAttributeMaxDynamicSharedMemorySize, smem);
    attn_kernel<<<dim3(TT, BB), 256, smem>>>(q, out);
}

// round 9
// speedup vs baseline: 1.0848x; 1.0848x over previous
#include <cuda_runtime.h>
#include <math.h>
#include <stdint.h>

// Problem constants
#define BB 8
#define TT 256
#define DD 256      // q_size / feature dim
#define HH 128
#define WW 128
#define CS 512      // c_size
#define MM (BB*TT)  // 2048 rows
#define RR 9
#define CC 9
#define KK 81       // R*C
#define ROWS 129    // H+1
#define COLS 129    // W+1
#define QTOT (8LL*256LL*16384LL)   // total floats in q
#define SD 257      // smem row stride for s[k][d] (257 % 32 == 1 -> bank spread)

// Scratch (device globals; no allocation allowed)
__device__ float g_h[MM * 256];   // pre-tanh hidden (W_p path)
__device__ float g_u[MM * 256];   // u = c_t @ W_a
__device__ float g_p[MM * 2];     // p_t

// ---------------------------------------------------------------------------
// Kernel 1: fused GEMM, scalar FFMA 4x4 micro-tile, transposed A tile
// (LDS.128 per fragment), double-buffered smem, software-pipelined LDG.
//   n <  256 : g_h[m][n]      = sum_c c_t[m,c] * W_p[n,c]
//   n >= 256 : g_u[m][n-256]  = sum_c c_t[m,c] * W_a[c,n-256]
// (R6 version — best measured: 48us)
// ---------------------------------------------------------------------------
__global__ __launch_bounds__(256)
void gemm_kernel(const float* __restrict__ A,   // c_t (2048,512)
                 const float* __restrict__ Wp,  // (256,512)
                 const float* __restrict__ Wa)  // (512,256)
{
    __shared__ float As[2][32][68];   // [buf][k][m], stride 68 -> 16B aligned cols
    __shared__ float Bs[2][32][64];   // [buf][k][n]

    const int m0 = blockIdx.x * 64;
    const int n0 = blockIdx.y * 64;
    const bool is_u = (n0 >= 256);
    const int tid = threadIdx.x;
    const int tx = tid & 15;        // 0..15 -> n (4 cols each)
    const int ty = tid >> 4;        // 0..15 -> m (4 rows each)

    const int a_row0 = tid >> 3;            // 0..31  (+32 for second)
    const int a_kk   = (tid & 7) << 2;      // 0,4,...,28
    const int bp_n0  = tid >> 3;
    const int bp_kk  = (tid & 7) << 2;
    const int ba_k0  = tid >> 4;            // 0..15 (+16 for second)
    const int ba_nn  = (tid & 15) << 2;

    float acc[4][4];
#pragma unroll
    for (int i = 0; i < 4; i++)
#pragma unroll
        for (int j = 0; j < 4; j++) acc[i][j] = 0.f;

    float4 ra[2], rb[2];

    // Prologue: fetch tile 0
    {
        const int k0 = 0;
#pragma unroll
        for (int s = 0; s < 2; s++)
            ra[s] = *(const float4*)(A + (size_t)(m0 + a_row0 + s * 32) * CS + k0 + a_kk);
        if (!is_u) {
#pragma unroll
            for (int s = 0; s < 2; s++)
                rb[s] = *(const float4*)(Wp + (size_t)(n0 + bp_n0 + s * 32) * CS + k0 + bp_kk);
        } else {
#pragma unroll
            for (int s = 0; s < 2; s++)
                rb[s] = *(const float4*)(Wa + (size_t)(k0 + ba_k0 + s * 16) * 256 + (n0 - 256) + ba_nn);
        }
#pragma unroll
        for (int s = 0; s < 2; s++) {
            int row = a_row0 + s * 32;
            As[0][a_kk + 0][row] = ra[s].x;
            As[0][a_kk + 1][row] = ra[s].y;
            As[0][a_kk + 2][row] = ra[s].z;
            As[0][a_kk + 3][row] = ra[s].w;
        }
        if (!is_u) {
#pragma unroll
            for (int s = 0; s < 2; s++) {
                int n = bp_n0 + s * 32;
                Bs[0][bp_kk + 0][n] = rb[s].x;
                Bs[0][bp_kk + 1][n] = rb[s].y;
                Bs[0][bp_kk + 2][n] = rb[s].z;
                Bs[0][bp_kk + 3][n] = rb[s].w;
            }
        } else {
#pragma unroll
            for (int s = 0; s < 2; s++)
                *(float4*)&Bs[0][ba_k0 + s * 16][ba_nn] = rb[s];
        }
    }
    __syncthreads();

    int buf = 0;
    for (int k0 = 0; k0 < CS; k0 += 32) {
        const int kn = k0 + 32;
        const bool more = (kn < CS);
        if (more) {
#pragma unroll
            for (int s = 0; s < 2; s++)
                ra[s] = *(const float4*)(A + (size_t)(m0 + a_row0 + s * 32) * CS + kn + a_kk);
            if (!is_u) {
#pragma unroll
                for (int s = 0; s < 2; s++)
                    rb[s] = *(const float4*)(Wp + (size_t)(n0 + bp_n0 + s * 32) * CS + kn + bp_kk);
            } else {
#pragma unroll
                for (int s = 0; s < 2; s++)
                    rb[s] = *(const float4*)(Wa + (size_t)(kn + ba_k0 + s * 16) * 256 + (n0 - 256) + ba_nn);
            }
        }
#pragma unroll
        for (int k = 0; k < 32; k++) {
            float4 a4 = *(const float4*)&As[buf][k][ty * 4];
            float4 b4 = *(const float4*)&Bs[buf][k][tx * 4];
            float a[4] = {a4.x, a4.y, a4.z, a4.w};
            float b[4] = {b4.x, b4.y, b4.z, b4.w};
#pragma unroll
            for (int i = 0; i < 4; i++)
#pragma unroll
                for (int j = 0; j < 4; j++)
                    acc[i][j] = fmaf(a[i], b[j], acc[i][j]);
        }
        if (more) {
            int nb = buf ^ 1;
#pragma unroll
            for (int s = 0; s < 2; s++) {
                int row = a_row0 + s * 32;
                As[nb][a_kk + 0][row] = ra[s].x;
                As[nb][a_kk + 1][row] = ra[s].y;
                As[nb][a_kk + 2][row] = ra[s].z;
                As[nb][a_kk + 3][row] = ra[s].w;
            }
            if (!is_u) {
#pragma unroll
                for (int s = 0; s < 2; s++) {
                    int n = bp_n0 + s * 32;
                    Bs[nb][bp_kk + 0][n] = rb[s].x;
                    Bs[nb][bp_kk + 1][n] = rb[s].y;
                    Bs[nb][bp_kk + 2][n] = rb[s].z;
                    Bs[nb][bp_kk + 3][n] = rb[s].w;
                }
            } else {
#pragma unroll
                for (int s = 0; s < 2; s++)
                    *(float4*)&Bs[nb][ba_k0 + s * 16][ba_nn] = rb[s];
            }
            __syncthreads();
        }
        buf ^= 1;
    }

#pragma unroll
    for (int i = 0; i < 4; i++) {
        int mrow = m0 + ty * 4 + i;
        float4 v = make_float4(acc[i][0], acc[i][1], acc[i][2], acc[i][3]);
        if (!is_u) *(float4*)&g_h[(size_t)mrow * 256 + n0 + tx * 4] = v;
        else       *(float4*)&g_u[(size_t)mrow * 256 + (n0 - 256) + tx * 4] = v;
    }
}

// ---------------------------------------------------------------------------
// Kernel 2: p_t = 128 * sigmoid( tanh(h) @ V_p^T ).  One warp per row,
// 8 rows per 256-thread block.
// ---------------------------------------------------------------------------
__global__ __launch_bounds__(256)
void p_kernel(const float* __restrict__ Vp)  // (2,256)
{
    const int m = blockIdx.x * 8 + (threadIdx.x >> 5);
    const int lane = threadIdx.x & 31;
    float s0 = 0.f, s1 = 0.f;
#pragma unroll
    for (int n = lane; n < 256; n += 32) {
        float hv = tanhf(g_h[(size_t)m * 256 + n]);
        s0 = fmaf(hv, Vp[n], s0);
        s1 = fmaf(hv, Vp[256 + n], s1);
    }
#pragma unroll
    for (int off = 16; off > 0; off >>= 1) {
        s0 += __shfl_xor_sync(0xffffffffu, s0, off);
        s1 += __shfl_xor_sync(0xffffffffu, s1, off);
    }
    if (lane == 0) {
        g_p[m * 2 + 0] = 128.f / (1.f + expf(-s0));
        g_p[m * 2 + 1] = 128.f / (1.f + expf(-s1));
    }
}

// ---------------------------------------------------------------------------
// Kernel 3: main local attention. One CTA per (b,t). 256 threads.
// smem window layout: s[k*SD + d]  (k = i*9+j window slot, d = feature).
// Gather is work-item based: item = (i*256 + d)*3 + part; consecutive lanes
// load consecutive 16B parts of the same 48B row-span -> warp-coalesced.
// Invalid slots hold finite garbage; they get softmax weight 0 via the mask.
// ---------------------------------------------------------------------------
__global__ __launch_bounds__(256)
void attn_kernel(const float* __restrict__ q, float* __restrict__ out)
{
    extern __shared__ float s[];           // [81][SD]
    __shared__ float su[256];
    __shared__ float spart[3 * KK];
    __shared__ float sa[KK];
    __shared__ float sw[KK];
    __shared__ float sred[2];
    __shared__ int   sri[RR], sci[CC];
    __shared__ float srex[RR], scex[CC];
    __shared__ int   scb;                  // rint(p1)

    const int t = blockIdx.x;
    const int b = blockIdx.y;
    const int m = b * TT + t;
    const int tid = threadIdx.x;

    // u vector
    su[tid] = g_u[(size_t)m * 256 + tid];
    const float p0 = g_p[m * 2 + 0];
    const float p1 = g_p[m * 2 + 1];

    // indices + gaussian terms
    if (tid < RR) {
        int cr = (int)rintf(p0);
        int v = cr + tid - 3;                  // round(p0) + off + 1, off = tid-4
        v = min(max(v, 0), ROWS);
        if (v == ROWS) v = 0;
        sri[tid] = v;
        float rr = (float)max(v - 1, 0);
        float d = (rr - p0) * 0.25f;
        srex[tid] = -2.f * d * d;
    } else if (tid < RR + CC) {
        int i = tid - RR;
        int cc = (int)rintf(p1);
        if (i == 0) scb = cc;
        int v = cc + i - 3;
        v = min(max(v, 0), COLS);
        if (v == COLS) v = 0;
        sci[i] = v;
        float ccf = (float)max(v - 1, 0);
        float d = (ccf - p1) * 0.25f;
        scex[i] = -2.f * d * d;
    }
    __syncthreads();

    // ---- Gather: 9 rows x 256 d x 3 float4-parts = 6912 items, 27/thread ----
    {
        const int cb = scb;
        const int a0 = (cb - 4) & ~3;          // aligned col start (may be -4)
        const int off = (cb - 4) & 3;          // uniform 0..3; j = 4*part + e - off
        const long long base_b = (long long)b * 4194304LL + a0;
#pragma unroll 9
        for (int it = 0; it < 27; ++it) {
            int item = tid + it * 256;
            int i    = item / 768;             // window row 0..8
            int rem  = item - i * 768;
            int d    = rem / 3;                // feature 0..255
            int part = rem - d * 3;            // 0..2
            int rv   = sri[i];
            float4 v = make_float4(0.f, 0.f, 0.f, 0.f);
            if (rv > 0) {
                long long g = base_b + (long long)d * 16384LL
                            + (long long)(rv - 1) * 128LL + part * 4;
                if (g >= 0 && g + 4 <= QTOT) {
                    v = __ldg((const float4*)(q + g));
                } else {
                    float f[4];
#pragma unroll
                    for (int x = 0; x < 4; x++) {
                        long long gg = g + x;
                        f[x] = (gg >= 0 && gg < QTOT) ? __ldg(q + gg) : 0.f;
                    }
                    v = make_float4(f[0], f[1], f[2], f[3]);
                }
            }
            // scatter the (up to 4) valid j's of this part
            int jb = 4 * part - off;           // j for element e: jb + e
            float vv[4] = {v.x, v.y, v.z, v.w};
#pragma unroll
            for (int e = 0; e < 4; e++) {
                int j = jb + e;
                if (j >= 0 && j < 9)
                    s[(i * 9 + j) * SD + d] = vv[e];
            }
        }
    }
    __syncthreads();

    // Scores: a[k] = sum_d u[d] * s[k][d], split over 3 d-partitions
    if (tid < 3 * KK) {
        int k = tid % KK;
        int part = tid / KK;
        const float* srow = &s[k * SD];
        float acc0 = 0.f, acc1 = 0.f;
        int d = part;
        for (; d + 3 < 256; d += 6) {
            acc0 = fmaf(su[d],     srow[d],     acc0);
            acc1 = fmaf(su[d + 3], srow[d + 3], acc1);
        }
        for (; d < 256; d += 3)
            acc0 = fmaf(su[d], srow[d], acc0);
        spart[part * KK + k] = acc0 + acc1;
    }
    __syncthreads();

    if (tid < KK) {
        float a = spart[tid] + spart[KK + tid] + spart[2 * KK + tid];
        int i = tid / CC, j = tid - i * CC;
        bool valid = (sri[i] > 0) && (sci[j] > 0);
        sa[tid] = valid ? a : -INFINITY;
    }
    __syncthreads();

    // max
    if (tid < 32) {
        float mx = -INFINITY;
        for (int k = tid; k < KK; k += 32) mx = fmaxf(mx, sa[k]);
#pragma unroll
        for (int off = 16; off > 0; off >>= 1)
            mx = fmaxf(mx, __shfl_xor_sync(0xffffffffu, mx, off));
        if (tid == 0) sred[0] = mx;
    }
    __syncthreads();
    const float mx = sred[0];
    if (tid < KK) sa[tid] = expf(sa[tid] - mx);
    __syncthreads();
    if (tid < 32) {
        float sm = 0.f;
        for (int k = tid; k < KK; k += 32) sm += sa[k];
#pragma unroll
        for (int off = 16; off > 0; off >>= 1)
            sm += __shfl_xor_sync(0xffffffffu, sm, off);
        if (tid == 0) sred[1] = sm;
    }
    __syncthreads();
    const float inv = 1.f / sred[1];
    if (tid < KK) {
        int i = tid / CC, j = tid - i * CC;
        float g = expf(srex[i] + scex[j]);
        sw[tid] = sa[tid] * inv * g;
    }
    __syncthreads();

    // Output: out[m][d] = sum_k w[k] * s[k][d], d = tid
    float o0 = 0.f, o1 = 0.f, o2 = 0.f, o3 = 0.f;
#pragma unroll
    for (int k = 0; k < 80; k += 4) {
        o0 = fmaf(sw[k + 0], s[(k + 0) * SD + tid], o0);
        o1 = fmaf(sw[k + 1], s[(k + 1) * SD + tid], o1);
        o2 = fmaf(sw[k + 2], s[(k + 2) * SD + tid], o2);
        o3 = fmaf(sw[k + 3], s[(k + 3) * SD + tid], o3);
    }
    o0 = fmaf(sw[80], s[80 * SD + tid], o0);
    out[(size_t)m * DD + tid] = (o0 + o1) + (o2 + o3);
}

// ---------------------------------------------------------------------------
extern "C" void kernel_launch(void* const* d_in, const int* in_sizes, int n_in,
                              void* d_out, int out_size)
{
    const float* q   = (const float*)d_in[0];   // (8,256,128,128)
    const float* c_t = (const float*)d_in[1];   // (8,256,512)
    const float* W_a = (const float*)d_in[2];   // (512,256)
    const float* W_p = (const float*)d_in[3];   // (256,512)
    const float* V_p = (const float*)d_in[4];   // (2,256)
    float* out = (float*)d_out;                 // (8,256,256)

    // Phase 1: projections (scalar pipelined GEMM — best measured)
    gemm_kernel<<<dim3(MM / 64, 512 / 64), 256>>>(c_t, W_p, W_a);
    // Phase 2: p_t
    p_kernel<<<MM / 8, 256>>>(V_p);
    // Phase 3: attention
    const int smem = KK * SD * (int)sizeof(float);  // 83268 bytes
    cudaFuncSetAttribute(attn_kernel, cudaFuncAttributeMaxDynamicSharedMemorySize, smem);
    attn_kernel<<<dim3(TT, BB), 256, smem>>>(q, out);
}

// round 10
// speedup vs baseline: 1.2553x; 1.1572x over previous
#include <cuda_runtime.h>
#include <math.h>
#include <stdint.h>

// Problem constants
#define BB 8
#define TT 256
#define DD 256      // q_size / feature dim
#define HH 128
#define WW 128
#define CS 512      // c_size
#define MM (BB*TT)  // 2048 rows
#define RR 9
#define CC 9
#define KK 81       // R*C
#define ROWS 129    // H+1
#define COLS 129    // W+1
#define QTOT (8LL*256LL*16384LL)   // total floats in q

// Scratch (device globals; no allocation allowed)
__device__ float g_h[MM * 256];   // pre-tanh hidden (W_p path)
__device__ float g_u[MM * 256];   // u = c_t @ W_a
__device__ float g_p[MM * 2];     // p_t

// ---------------------------------------------------------------------------
// Kernel 1: fused GEMM, scalar FFMA 8x4 micro-tile, BM=64 BN=64 BK=16,
// 128 threads, transposed A tile (LDS.128 frags), double-buffered,
// software-pipelined LDG.
//   n <  256 : g_h[m][n]      = sum_c c_t[m,c] * W_p[n,c]
//   n >= 256 : g_u[m][n-256]  = sum_c c_t[m,c] * W_a[c,n-256]
// ---------------------------------------------------------------------------
__global__ __launch_bounds__(128)
void gemm_kernel(const float* __restrict__ A,   // c_t (2048,512)
                 const float* __restrict__ Wp,  // (256,512)
                 const float* __restrict__ Wa)  // (512,256)
{
    __shared__ float As[2][16][68];   // [buf][k][m], stride 68 -> 16B aligned
    __shared__ float Bs[2][16][64];   // [buf][k][n]

    const int m0 = blockIdx.x * 64;
    const int n0 = blockIdx.y * 64;
    const bool is_u = (n0 >= 256);
    const int tid = threadIdx.x;
    const int tx = tid & 15;        // 0..15 -> n (4 cols each)
    const int ty = tid >> 4;        // 0..7  -> m (8 rows each)

    // Per-thread load coordinates (2 float4 each for A and B)
    const int a_row = tid >> 2;             // 0..31 (f = tid + s*128 -> row = f>>2)
    const int a_kk  = (tid & 3) << 2;       // 0,4,8,12
    const int bp_n  = tid >> 2;             // Wp: n = f>>2
    const int bp_kk = (tid & 3) << 2;
    const int ba_k  = tid >> 4;             // Wa: k = f>>4 (0..7, +8 for second)
    const int ba_nn = (tid & 15) << 2;

    float acc[8][4];
#pragma unroll
    for (int i = 0; i < 8; i++)
#pragma unroll
        for (int j = 0; j < 4; j++) acc[i][j] = 0.f;

    float4 ra[2], rb[2];

    auto ldg_tile = [&](int k0) {
#pragma unroll
        for (int s = 0; s < 2; s++)
            ra[s] = *(const float4*)(A + (size_t)(m0 + a_row + s * 32) * CS + k0 + a_kk);
        if (!is_u) {
#pragma unroll
            for (int s = 0; s < 2; s++)
                rb[s] = *(const float4*)(Wp + (size_t)(n0 + bp_n + s * 32) * CS + k0 + bp_kk);
        } else {
#pragma unroll
            for (int s = 0; s < 2; s++)
                rb[s] = *(const float4*)(Wa + (size_t)(k0 + ba_k + s * 8) * 256 + (n0 - 256) + ba_nn);
        }
    };

    auto sts_tile = [&](int bf) {
#pragma unroll
        for (int s = 0; s < 2; s++) {
            int row = a_row + s * 32;
            As[bf][a_kk + 0][row] = ra[s].x;
            As[bf][a_kk + 1][row] = ra[s].y;
            As[bf][a_kk + 2][row] = ra[s].z;
            As[bf][a_kk + 3][row] = ra[s].w;
        }
        if (!is_u) {
#pragma unroll
            for (int s = 0; s < 2; s++) {
                int n = bp_n + s * 32;
                Bs[bf][bp_kk + 0][n] = rb[s].x;
                Bs[bf][bp_kk + 1][n] = rb[s].y;
                Bs[bf][bp_kk + 2][n] = rb[s].z;
                Bs[bf][bp_kk + 3][n] = rb[s].w;
            }
        } else {
#pragma unroll
            for (int s = 0; s < 2; s++)
                *(float4*)&Bs[bf][ba_k + s * 8][ba_nn] = rb[s];
        }
    };

    // Prologue: tile 0
    ldg_tile(0);
    sts_tile(0);
    __syncthreads();

    int buf = 0;
    for (int t = 0; t < 32; t++) {
        const bool more = (t < 31);
        if (more) ldg_tile((t + 1) * 16);
#pragma unroll
        for (int k = 0; k < 16; k++) {
            float4 a4 = *(const float4*)&As[buf][k][ty * 8];
            float4 a5 = *(const float4*)&As[buf][k][ty * 8 + 4];
            float4 b4 = *(const float4*)&Bs[buf][k][tx * 4];
            float a[8] = {a4.x, a4.y, a4.z, a4.w, a5.x, a5.y, a5.z, a5.w};
            float b[4] = {b4.x, b4.y, b4.z, b4.w};
#pragma unroll
            for (int i = 0; i < 8; i++)
#pragma unroll
                for (int j = 0; j < 4; j++)
                    acc[i][j] = fmaf(a[i], b[j], acc[i][j]);
        }
        if (more) { sts_tile(buf ^ 1); __syncthreads(); }
        buf ^= 1;
    }

    // Epilogue: 8 rows x 4 cols per thread, one float4 store per row
#pragma unroll
    for (int i = 0; i < 8; i++) {
        int mrow = m0 + ty * 8 + i;
        float4 v = make_float4(acc[i][0], acc[i][1], acc[i][2], acc[i][3]);
        if (!is_u) *(float4*)&g_h[(size_t)mrow * 256 + n0 + tx * 4] = v;
        else       *(float4*)&g_u[(size_t)mrow * 256 + (n0 - 256) + tx * 4] = v;
    }
}

// ---------------------------------------------------------------------------
// Kernel 2: p_t = 128 * sigmoid( tanh(h) @ V_p^T ).  One warp per row,
// 8 rows per 256-thread block.
// ---------------------------------------------------------------------------
__global__ __launch_bounds__(256)
void p_kernel(const float* __restrict__ Vp)  // (2,256)
{
    const int m = blockIdx.x * 8 + (threadIdx.x >> 5);
    const int lane = threadIdx.x & 31;
    float s0 = 0.f, s1 = 0.f;
#pragma unroll
    for (int n = lane; n < 256; n += 32) {
        float hv = tanhf(g_h[(size_t)m * 256 + n]);
        s0 = fmaf(hv, Vp[n], s0);
        s1 = fmaf(hv, Vp[256 + n], s1);
    }
#pragma unroll
    for (int off = 16; off > 0; off >>= 1) {
        s0 += __shfl_xor_sync(0xffffffffu, s0, off);
        s1 += __shfl_xor_sync(0xffffffffu, s1, off);
    }
    if (lane == 0) {
        g_p[m * 2 + 0] = 128.f / (1.f + expf(-s0));
        g_p[m * 2 + 1] = 128.f / (1.f + expf(-s1));
    }
}

// ---------------------------------------------------------------------------
// Vectorized gather: each thread owns feature d = tid and loads its 9 window
// rows as 3 aligned float4s covering cols a0..a0+11; the 9 needed values sit
// at uniform offset OFF = (cb-4)&3. Invalid slots (clipped/wrapped -> NaN in
// reference) get softmax weight 0, so any finite value is acceptable there.
// ---------------------------------------------------------------------------
template<int OFF>
__device__ __forceinline__ void gather_rows(const float* __restrict__ q,
                                            long long gbase,   // b*4194304 + d*16384 + a0
                                            const int* __restrict__ sri,
                                            float* __restrict__ srow)  // &s[d*81]
{
#pragma unroll 3
    for (int i = 0; i < 9; i++) {
        int rv = sri[i];
        float f[12];
        if (rv > 0) {
            long long g = gbase + (long long)(rv - 1) * 128;
            if (g >= 0 && g + 12 <= QTOT) {
                float4 v0 = __ldg((const float4*)(q + g));
                float4 v1 = __ldg((const float4*)(q + g + 4));
                float4 v2 = __ldg((const float4*)(q + g + 8));
                f[0] = v0.x; f[1] = v0.y; f[2]  = v0.z; f[3]  = v0.w;
                f[4] = v1.x; f[5] = v1.y; f[6]  = v1.z; f[7]  = v1.w;
                f[8] = v2.x; f[9] = v2.y; f[10] = v2.z; f[11] = v2.w;
            } else {
                // Rare buffer-edge fallback
#pragma unroll
                for (int x = 0; x < 12; x++) {
                    long long gg = g + x;
                    f[x] = (gg >= 0 && gg < QTOT) ? __ldg(q + gg) : 0.f;
                }
            }
        } else {
#pragma unroll
            for (int x = 0; x < 12; x++) f[x] = 0.f;
        }
#pragma unroll
        for (int j = 0; j < 9; j++) srow[i * 9 + j] = f[OFF + j];
    }
}

// ---------------------------------------------------------------------------
// Kernel 3: main local attention. One CTA per (b,t). 256 threads.
// (R6 version — best measured)
// ---------------------------------------------------------------------------
__global__ __launch_bounds__(256)
void attn_kernel(const float* __restrict__ q, float* __restrict__ out)
{
    extern __shared__ float s[];           // [256][81] window, layout d*81+k
    __shared__ float su[256];
    __shared__ float spart[3 * KK];
    __shared__ float sa[KK];
    __shared__ float sw[KK];
    __shared__ float sred[2];
    __shared__ int   sri[RR], sci[CC];
    __shared__ float srex[RR], scex[CC];
    __shared__ int   scb;                  // rint(p1)

    const int t = blockIdx.x;
    const int b = blockIdx.y;
    const int m = b * TT + t;
    const int tid = threadIdx.x;

    // u vector
    su[tid] = g_u[(size_t)m * 256 + tid];
    const float p0 = g_p[m * 2 + 0];
    const float p1 = g_p[m * 2 + 1];

    // indices + gaussian terms
    if (tid < RR) {
        int cr = (int)rintf(p0);
        int v = cr + tid - 3;                  // round(p0) + off + 1, off = tid-4
        v = min(max(v, 0), ROWS);
        if (v == ROWS) v = 0;
        sri[tid] = v;
        float rr = (float)max(v - 1, 0);
        float d = (rr - p0) * 0.25f;
        srex[tid] = -2.f * d * d;
    } else if (tid < RR + CC) {
        int i = tid - RR;
        int cc = (int)rintf(p1);
        if (i == 0) scb = cc;
        int v = cc + i - 3;
        v = min(max(v, 0), COLS);
        if (v == COLS) v = 0;
        sci[i] = v;
        float ccf = (float)max(v - 1, 0);
        float d = (ccf - p1) * 0.25f;
        scex[i] = -2.f * d * d;
    }
    __syncthreads();

    // Gather window into smem: s[d*81 + k], k = i*9 + j, d = tid
    {
        const int cb = scb;
        const int a0 = (cb - 4) & ~3;          // aligned col start (may be -4)
        const int off = (cb - 4) & 3;          // uniform 0..3
        const long long gbase = (long long)b * 4194304LL
                              + (long long)tid * 16384LL + a0;
        float* srow = &s[tid * KK];
        switch (off) {
            case 0: gather_rows<0>(q, gbase, sri, srow); break;
            case 1: gather_rows<1>(q, gbase, sri, srow); break;
            case 2: gather_rows<2>(q, gbase, sri, srow); break;
            default: gather_rows<3>(q, gbase, sri, srow); break;
        }
    }
    __syncthreads();

    // Scores: a[k] = sum_d u[d] * s[d][k], split over 3 d-partitions
    if (tid < 3 * KK) {
        int k = tid % KK;
        int part = tid / KK;
        float acc0 = 0.f, acc1 = 0.f;
        int d = part;
        for (; d + 3 < 256; d += 6) {
            acc0 = fmaf(su[d],     s[d * KK + k],       acc0);
            acc1 = fmaf(su[d + 3], s[(d + 3) * KK + k], acc1);
        }
        for (; d < 256; d += 3)
            acc0 = fmaf(su[d], s[d * KK + k], acc0);
        spart[part * KK + k] = acc0 + acc1;
    }
    __syncthreads();

    if (tid < KK) {
        float a = spart[tid] + spart[KK + tid] + spart[2 * KK + tid];
        int i = tid / CC, j = tid - i * CC;
        bool valid = (sri[i] > 0) && (sci[j] > 0);
        sa[tid] = valid ? a : -INFINITY;
    }
    __syncthreads();

    // max
    if (tid < 32) {
        float mx = -INFINITY;
        for (int k = tid; k < KK; k += 32) mx = fmaxf(mx, sa[k]);
#pragma unroll
        for (int off = 16; off > 0; off >>= 1)
            mx = fmaxf(mx, __shfl_xor_sync(0xffffffffu, mx, off));
        if (tid == 0) sred[0] = mx;
    }
    __syncthreads();
    const float mx = sred[0];
    if (tid < KK) sa[tid] = expf(sa[tid] - mx);
    __syncthreads();
    if (tid < 32) {
        float sm = 0.f;
        for (int k = tid; k < KK; k += 32) sm += sa[k];
#pragma unroll
        for (int off = 16; off > 0; off >>= 1)
            sm += __shfl_xor_sync(0xffffffffu, sm, off);
        if (tid == 0) sred[1] = sm;
    }
    __syncthreads();
    const float inv = 1.f / sred[1];
    if (tid < KK) {
        int i = tid / CC, j = tid - i * CC;
        float g = expf(srex[i] + scex[j]);
        sw[tid] = sa[tid] * inv * g;
    }
    __syncthreads();

    // Output: out[m][d] = sum_k w[k] * s[d][k]
    float o0 = 0.f, o1 = 0.f, o2 = 0.f, o3 = 0.f;
    const float* sd = &s[tid * KK];
#pragma unroll
    for (int k = 0; k < 80; k += 4) {
        o0 = fmaf(sw[k + 0], sd[k + 0], o0);
        o1 = fmaf(sw[k + 1], sd[k + 1], o1);
        o2 = fmaf(sw[k + 2], sd[k + 2], o2);
        o3 = fmaf(sw[k + 3], sd[k + 3], o3);
    }
    o0 = fmaf(sw[80], sd[80], o0);
    out[(size_t)m * DD + tid] = (o0 + o1) + (o2 + o3);
}

// ---------------------------------------------------------------------------
extern "C" void kernel_launch(void* const* d_in, const int* in_sizes, int n_in,
                              void* d_out, int out_size)
{
    const float* q   = (const float*)d_in[0];   // (8,256,128,128)
    const float* c_t = (const float*)d_in[1];   // (8,256,512)
    const float* W_a = (const float*)d_in[2];   // (512,256)
    const float* W_p = (const float*)d_in[3];   // (256,512)
    const float* V_p = (const float*)d_in[4];   // (2,256)
    float* out = (float*)d_out;                 // (8,256,256)

    // Phase 1: projections (8x4 micro-tile scalar GEMM)
    gemm_kernel<<<dim3(MM / 64, 512 / 64), 128>>>(c_t, W_p, W_a);
    // Phase 2: p_t
    p_kernel<<<MM / 8, 256>>>(V_p);
    // Phase 3: attention (R6 version)
    const int smem = KK * DD * (int)sizeof(float);  // 82944 bytes
    cudaFuncSetAttribute(attn_kernel, cudaFuncAttributeMaxDynamicSharedMemorySize, smem);
    attn_kernel<<<dim3(TT, BB), 256, smem>>>(q, out);
}